// round 7
// baseline (speedup 1.0000x reference)
#include <cuda_runtime.h>
#include <math.h>

#define NCTA   128
#define NTHR   256
#define NWRP   8
#define HID    1024
#define GATES  4096
#define LATENT 2048
#define SEQ    16
// smem: wbuf 32*1024 floats (== SEQ*LATENT phase-A staging, unioned) + hbuf 1024
#define SMEM_FLOATS (32 * 1024 + 1024)
#define SMEM_BYTES  (SMEM_FLOATS * 4)   // 132KB -> 1 CTA/SM

// ---------------- device scratch (no allocation allowed) ----------------
__device__ float    g_xg[SEQ * GATES];  // gate pre-activations, current layer
__device__ float    g_h1[SEQ * HID];    // layer-0 hidden outputs (per-step rows)
__device__ unsigned g_bar;              // flip-bit grid barrier (zero-init,
                                        // wrap-safe, never reset -> replay-safe)

// ---------------- grid barrier: cooperative-groups flip-bit algorithm ----
__device__ __forceinline__ void grid_barrier() {
    __syncthreads();
    if (threadIdx.x == 0) {
        __threadfence();   // release
        unsigned nb = (blockIdx.x == 0) ? (0x80000000u - (NCTA - 1u)) : 1u;
        unsigned old = atomicAdd(&g_bar, nb);
        while ((((old ^ *(volatile unsigned*)&g_bar)) & 0x80000000u) == 0u) { }
        __threadfence();   // acquire
    }
    __syncthreads();
}

__device__ __forceinline__ float sigmoidf_(float x) {
    return 1.0f / (1.0f + __expf(-x));
}

// L1-bypassing accessors for cross-CTA mutable data
__device__ __forceinline__ float4 ldcg4(const float4* p) {
    float4 v;
    asm volatile("ld.global.cg.v4.f32 {%0,%1,%2,%3}, [%4];"
                 : "=f"(v.x), "=f"(v.y), "=f"(v.z), "=f"(v.w) : "l"(p) : "memory");
    return v;
}
__device__ __forceinline__ float ldcg1(const float* p) {
    float v;
    asm volatile("ld.global.cg.f32 %0, [%1];" : "=f"(v) : "l"(p) : "memory");
    return v;
}
__device__ __forceinline__ void stcg1(float* p, float v) {
    asm volatile("st.global.cg.f32 [%0], %1;" :: "l"(p), "f"(v) : "memory");
}

// ---------------- input GEMM phase (R4/R6-verbatim math) --------------------
// out[t][row] = inp[t] . W[row] + b1[row] + b2[row]; warp gw owns rows 4gw..+3.
template <int D>
__device__ void gate_gemm_dev(const float* __restrict__ W,
                              const float* __restrict__ inp,
                              const float* __restrict__ b1,
                              const float* __restrict__ b2,
                              float* __restrict__ out,
                              float* smem) {
    const int tid  = threadIdx.x;
    const int lane = tid & 31;
    const int warp = tid >> 5;
    const int NF4  = D / 4;

    const float4* in4 = (const float4*)inp;
    float4* s4 = (float4*)smem;
    for (int i = tid; i < SEQ * D / 4; i += NTHR) s4[i] = ldcg4(&in4[i]);
    __syncthreads();
    const float4* xs4 = (const float4*)smem;

    const int row = (blockIdx.x * NWRP + warp) * 4;   // 128*8 warps == GATES/4

    float acc[4][SEQ];
#pragma unroll
    for (int r = 0; r < 4; r++)
#pragma unroll
        for (int t = 0; t < SEQ; t++) acc[r][t] = 0.0f;

    const float4* w0 = (const float4*)(W + (size_t)(row + 0) * D);
    const float4* w1 = (const float4*)(W + (size_t)(row + 1) * D);
    const float4* w2 = (const float4*)(W + (size_t)(row + 2) * D);
    const float4* w3 = (const float4*)(W + (size_t)(row + 3) * D);

    for (int ci = lane; ci < NF4; ci += 32) {
        float4 a0 = w0[ci], a1 = w1[ci], a2 = w2[ci], a3 = w3[ci];
#pragma unroll
        for (int t = 0; t < SEQ; t++) {
            float4 xv = xs4[t * NF4 + ci];
            acc[0][t] += a0.x * xv.x + a0.y * xv.y + a0.z * xv.z + a0.w * xv.w;
            acc[1][t] += a1.x * xv.x + a1.y * xv.y + a1.z * xv.z + a1.w * xv.w;
            acc[2][t] += a2.x * xv.x + a2.y * xv.y + a2.z * xv.z + a2.w * xv.w;
            acc[3][t] += a3.x * xv.x + a3.y * xv.y + a3.z * xv.z + a3.w * xv.w;
        }
    }
#pragma unroll
    for (int r = 0; r < 4; r++) {
#pragma unroll
        for (int t = 0; t < SEQ; t++) {
            float s = acc[r][t];
#pragma unroll
            for (int off = 16; off; off >>= 1)
                s += __shfl_xor_sync(0xffffffffu, s, off);
            if (lane == 0)
                stcg1(&out[t * GATES + row + r], s + b1[row + r] + b2[row + r]);
        }
    }
}

// ---------------- one LSTM layer, w_hh SMEM-resident ------------------------
// CTA owns 8 hidden units j = blockIdx*8 + w (warp w). wbuf holds their 32
// gate rows (128 KB) for the whole layer; each step only touches SMEM + a
// 4 KB h broadcast from L2. Math identical to R4/R6 step.
__device__ void lstm_layer_dev(const float* __restrict__ whh,
                               const float* __restrict__ xg,
                               float* __restrict__ hbase,    // SEQ rows out
                               float* __restrict__ last_out, // null or HID
                               float* smem) {
    float* wbuf = smem;                 // 32 * 1024 floats
    float* hbuf = smem + 32 * 1024;     // 1024 floats

    const int tid  = threadIdx.x;
    const int lane = tid & 31;
    const int warp = tid >> 5;
    const int j    = blockIdx.x * NWRP + warp;

    // stage this CTA's w_hh slice: local row r = w*4+g  <->  global row g*HID + (blockIdx*8+w)
    for (int idx = tid; idx < 32 * HID; idx += NTHR) {
        int r = idx >> 10;
        int k = idx & 1023;
        int w = r >> 2, g = r & 3;
        wbuf[idx] = whh[(size_t)(g * HID + (blockIdx.x * NWRP + w)) * HID + k];
    }
    __syncthreads();

    float c = 0.0f;
    for (int t = 0; t < SEQ; t++) {
        float dot[4] = {0.f, 0.f, 0.f, 0.f};
        if (t > 0) {
            const float4* hp4 = (const float4*)(hbase + (t - 1) * HID);
            float4* hs4 = (float4*)hbuf;
            for (int i = tid; i < HID / 4; i += NTHR) hs4[i] = ldcg4(&hp4[i]);
            __syncthreads();

            float4 hv[8];
#pragma unroll
            for (int q = 0; q < 8; q++) hv[q] = hs4[lane + 32 * q];

#pragma unroll
            for (int g = 0; g < 4; g++) {
                const float4* wr = (const float4*)(wbuf + (warp * 4 + g) * HID);
                float s = 0.0f;
#pragma unroll
                for (int q = 0; q < 8; q++) {
                    float4 w = wr[lane + 32 * q];
                    s += w.x * hv[q].x + w.y * hv[q].y + w.z * hv[q].z + w.w * hv[q].w;
                }
                dot[g] = s;
            }
#pragma unroll
            for (int g = 0; g < 4; g++)
#pragma unroll
                for (int off = 16; off; off >>= 1)
                    dot[g] += __shfl_xor_sync(0xffffffffu, dot[g], off);
        }

        if (lane == 0) {
            const float* xgt = xg + t * GATES;
            float gi = ldcg1(&xgt[0 * HID + j]) + dot[0];
            float gf = ldcg1(&xgt[1 * HID + j]) + dot[1];
            float gg = ldcg1(&xgt[2 * HID + j]) + dot[2];
            float go = ldcg1(&xgt[3 * HID + j]) + dot[3];
            float iv = sigmoidf_(gi);
            float fv = sigmoidf_(gf);
            float gv = tanhf(gg);
            float ov = sigmoidf_(go);
            float cn = fv * c + iv * gv;
            c = cn;
            float hval = ov * tanhf(cn);
            stcg1(&hbase[t * HID + j], hval);
            if (last_out && t == SEQ - 1) stcg1(&last_out[j], hval);
        }
        grid_barrier();   // publish h_t before anyone reads it at t+1
    }
}

// ---------------- single persistent kernel ----------------------------------
__global__ void __launch_bounds__(NTHR, 1)
lstm2_persist(const float* __restrict__ x,
              const float* __restrict__ w_ih0, const float* __restrict__ w_hh0,
              const float* __restrict__ b_ih0, const float* __restrict__ b_hh0,
              const float* __restrict__ w_ih1, const float* __restrict__ w_hh1,
              const float* __restrict__ b_ih1, const float* __restrict__ b_hh1,
              float* __restrict__ out) {
    extern __shared__ float smem[];

    // Phase A: xg = x @ w_ih0^T + b_ih0 + b_hh0
    gate_gemm_dev<LATENT>(w_ih0, x, b_ih0, b_hh0, g_xg, smem);
    grid_barrier();

    // Layer 0 recurrence (w_hh0 SMEM-resident; h rows per-step disjoint)
    lstm_layer_dev(w_hh0, g_xg, g_h1, nullptr, smem);

    // Phase C: xg = h1 @ w_ih1^T + b_ih1 + b_hh1
    gate_gemm_dev<HID>(w_ih1, g_h1, b_ih1, b_hh1, g_xg, smem);
    grid_barrier();

    // Layer 1 recurrence -> out: [0:HID) last_output, [HID:) h2 rows
    lstm_layer_dev(w_hh1, g_xg, out + HID, out, smem);
}

// ---------------- host launch (graph-capturable, single node) ---------------
extern "C" void kernel_launch(void* const* d_in, const int* in_sizes, int n_in,
                              void* d_out, int out_size) {
    const float* x     = (const float*)d_in[0];
    const float* w_ih0 = (const float*)d_in[1];
    const float* w_hh0 = (const float*)d_in[2];
    const float* b_ih0 = (const float*)d_in[3];
    const float* b_hh0 = (const float*)d_in[4];
    const float* w_ih1 = (const float*)d_in[5];
    const float* w_hh1 = (const float*)d_in[6];
    const float* b_ih1 = (const float*)d_in[7];
    const float* b_hh1 = (const float*)d_in[8];
    float* out = (float*)d_out;

    cudaFuncSetAttribute(lstm2_persist,
                         cudaFuncAttributeMaxDynamicSharedMemorySize, SMEM_BYTES);
    lstm2_persist<<<NCTA, NTHR, SMEM_BYTES>>>(x, w_ih0, w_hh0, b_ih0, b_hh0,
                                              w_ih1, w_hh1, b_ih1, b_hh1, out);
}

// round 8
// speedup vs baseline: 1.0228x; 1.0228x over previous
#include <cuda_runtime.h>
#include <math.h>

#define NCTA   128
#define NTHR   256
#define NWRP   8
#define HID    1024
#define GATES  4096
#define LATENT 2048
#define SEQ    16
#define SMEM_BYTES (SEQ * HID * 4)   // 64KB: phase-C h1 staging only

// ---------------- device scratch (no allocation allowed) ----------------
__device__ float    g_xg[SEQ * GATES];  // gate pre-activations, current layer
__device__ float    g_h1[SEQ * HID];    // layer-0 hidden outputs (per-step rows)
__device__ unsigned g_bar;              // flip-bit grid barrier (zero-init,
                                        // wrap-safe, never reset -> replay-safe)

// ------- grid barrier: flip-bit, release-atomic + acquire-poll (no MEMBARs) --
__device__ __forceinline__ void grid_barrier() {
    __syncthreads();
    if (threadIdx.x == 0) {
        unsigned nb = (blockIdx.x == 0) ? (0x80000000u - (NCTA - 1u)) : 1u;
        unsigned old;
        asm volatile("atom.add.release.gpu.global.u32 %0, [%1], %2;"
                     : "=r"(old) : "l"(&g_bar), "r"(nb) : "memory");
        unsigned cur;
        do {
            asm volatile("ld.acquire.gpu.global.u32 %0, [%1];"
                         : "=r"(cur) : "l"(&g_bar) : "memory");
        } while (((old ^ cur) & 0x80000000u) == 0u);
    }
    __syncthreads();
}

__device__ __forceinline__ float sigmoidf_(float x) {
    return 1.0f / (1.0f + __expf(-x));
}

// L1-bypassing accessors for cross-CTA mutable data
__device__ __forceinline__ float4 ldcg4(const float4* p) {
    float4 v;
    asm volatile("ld.global.cg.v4.f32 {%0,%1,%2,%3}, [%4];"
                 : "=f"(v.x), "=f"(v.y), "=f"(v.z), "=f"(v.w) : "l"(p) : "memory");
    return v;
}
__device__ __forceinline__ float ldcg1(const float* p) {
    float v;
    asm volatile("ld.global.cg.f32 %0, [%1];" : "=f"(v) : "l"(p) : "memory");
    return v;
}
__device__ __forceinline__ void stcg1(float* p, float v) {
    asm volatile("st.global.cg.f32 [%0], %1;" :: "l"(p), "f"(v) : "memory");
}

// ---------------- input GEMM phase (R6-verbatim arithmetic) -----------------
// out[t][row] = inp[t].W[row] + b1 + b2; warp gw owns rows 4gw..4gw+3.
// FROM_SMEM=true : stage inp (mutable, cross-CTA-written) into SMEM via ld.cg.
// FROM_SMEM=false: inp immutable (x) -> plain LDG, L1-served.
template <int D, bool FROM_SMEM>
__device__ void gate_gemm_dev(const float* __restrict__ W,
                              const float* __restrict__ inp,
                              const float* __restrict__ b1,
                              const float* __restrict__ b2,
                              float* __restrict__ out,
                              float* smem) {
    const int tid  = threadIdx.x;
    const int lane = tid & 31;
    const int warp = tid >> 5;
    const int NF4  = D / 4;

    const float4* xs4;
    if (FROM_SMEM) {
        const float4* in4 = (const float4*)inp;
        float4* s4 = (float4*)smem;
        for (int i = tid; i < SEQ * D / 4; i += NTHR) s4[i] = ldcg4(&in4[i]);
        __syncthreads();
        xs4 = (const float4*)smem;
    } else {
        xs4 = (const float4*)inp;
    }

    const int row = (blockIdx.x * NWRP + warp) * 4;   // 128*8 warps == GATES/4

    float acc[4][SEQ];
#pragma unroll
    for (int r = 0; r < 4; r++)
#pragma unroll
        for (int t = 0; t < SEQ; t++) acc[r][t] = 0.0f;

    const float4* w0 = (const float4*)(W + (size_t)(row + 0) * D);
    const float4* w1 = (const float4*)(W + (size_t)(row + 1) * D);
    const float4* w2 = (const float4*)(W + (size_t)(row + 2) * D);
    const float4* w3 = (const float4*)(W + (size_t)(row + 3) * D);

    for (int ci = lane; ci < NF4; ci += 32) {
        float4 a0 = w0[ci], a1 = w1[ci], a2 = w2[ci], a3 = w3[ci];
#pragma unroll
        for (int t = 0; t < SEQ; t++) {
            float4 xv = xs4[t * NF4 + ci];
            acc[0][t] += a0.x * xv.x + a0.y * xv.y + a0.z * xv.z + a0.w * xv.w;
            acc[1][t] += a1.x * xv.x + a1.y * xv.y + a1.z * xv.z + a1.w * xv.w;
            acc[2][t] += a2.x * xv.x + a2.y * xv.y + a2.z * xv.z + a2.w * xv.w;
            acc[3][t] += a3.x * xv.x + a3.y * xv.y + a3.z * xv.z + a3.w * xv.w;
        }
    }
#pragma unroll
    for (int r = 0; r < 4; r++) {
#pragma unroll
        for (int t = 0; t < SEQ; t++) {
            float s = acc[r][t];
#pragma unroll
            for (int off = 16; off; off >>= 1)
                s += __shfl_xor_sync(0xffffffffu, s, off);
            if (lane == 0)
                stcg1(&out[t * GATES + row + r], s + b1[row + r] + b2[row + r]);
        }
    }
}

// ---------------- one LSTM layer: latency-lean step loop --------------------
// Warp (blockIdx*8+warp) owns hidden unit j. Per step: 8 direct ld.cg.v4 of h
// (no SMEM staging, no syncthreads), weights via plain LDG (immutable ->
// L1-cached across steps), xg biases preloaded into lanes 0..15 and shuffled.
__device__ void lstm_layer_dev(const float* __restrict__ whh,
                               const float* __restrict__ xg,
                               float* __restrict__ hbase,     // SEQ rows out
                               float* __restrict__ last_out) { // null or HID
    const int lane = threadIdx.x & 31;
    const int warp = threadIdx.x >> 5;
    const int j    = blockIdx.x * NWRP + warp;

    // preload this unit's 4 gate biases for all 16 steps: lane t holds step t
    float xgi = 0.f, xgf = 0.f, xgg = 0.f, xgo = 0.f;
    if (lane < SEQ) {
        const float* xgt = xg + lane * GATES;
        xgi = ldcg1(&xgt[0 * HID + j]);
        xgf = ldcg1(&xgt[1 * HID + j]);
        xgg = ldcg1(&xgt[2 * HID + j]);
        xgo = ldcg1(&xgt[3 * HID + j]);
    }

    const float4* w0 = (const float4*)(whh + (size_t)(0 * HID + j) * HID);
    const float4* w1 = (const float4*)(whh + (size_t)(1 * HID + j) * HID);
    const float4* w2 = (const float4*)(whh + (size_t)(2 * HID + j) * HID);
    const float4* w3 = (const float4*)(whh + (size_t)(3 * HID + j) * HID);

    float c = 0.0f;
    for (int t = 0; t < SEQ; t++) {
        float dot[4] = {0.f, 0.f, 0.f, 0.f};
        if (t > 0) {
            const float4* hp4 = (const float4*)(hbase + (t - 1) * HID);
            float4 hv[8];
#pragma unroll
            for (int q = 0; q < 8; q++) hv[q] = ldcg4(&hp4[lane + 32 * q]);

            float s0 = 0.f, s1 = 0.f, s2 = 0.f, s3 = 0.f;
#pragma unroll
            for (int q = 0; q < 8; q++) {
                float4 a0 = w0[lane + 32 * q];
                float4 a1 = w1[lane + 32 * q];
                float4 a2 = w2[lane + 32 * q];
                float4 a3 = w3[lane + 32 * q];
                s0 += a0.x * hv[q].x + a0.y * hv[q].y + a0.z * hv[q].z + a0.w * hv[q].w;
                s1 += a1.x * hv[q].x + a1.y * hv[q].y + a1.z * hv[q].z + a1.w * hv[q].w;
                s2 += a2.x * hv[q].x + a2.y * hv[q].y + a2.z * hv[q].z + a2.w * hv[q].w;
                s3 += a3.x * hv[q].x + a3.y * hv[q].y + a3.z * hv[q].z + a3.w * hv[q].w;
            }
            dot[0] = s0; dot[1] = s1; dot[2] = s2; dot[3] = s3;
#pragma unroll
            for (int g = 0; g < 4; g++)
#pragma unroll
                for (int off = 16; off; off >>= 1)
                    dot[g] += __shfl_xor_sync(0xffffffffu, dot[g], off);
        }

        // step-t biases arrive by shuffle from lane t (all lanes converged)
        float bi = __shfl_sync(0xffffffffu, xgi, t);
        float bf = __shfl_sync(0xffffffffu, xgf, t);
        float bg = __shfl_sync(0xffffffffu, xgg, t);
        float bo = __shfl_sync(0xffffffffu, xgo, t);

        if (lane == 0) {
            float gi = bi + dot[0];
            float gf = bf + dot[1];
            float gg = bg + dot[2];
            float go = bo + dot[3];
            float iv = sigmoidf_(gi);
            float fv = sigmoidf_(gf);
            float gv = tanhf(gg);
            float ov = sigmoidf_(go);
            float cn = fv * c + iv * gv;
            c = cn;
            float hval = ov * tanhf(cn);
            stcg1(&hbase[t * HID + j], hval);
            if (last_out && t == SEQ - 1) stcg1(&last_out[j], hval);
        }
        // publish h_t; the very last step of the final layer needs no barrier
        if (!(last_out && t == SEQ - 1)) grid_barrier();
    }
}

// ---------------- single persistent kernel ----------------------------------
__global__ void __launch_bounds__(NTHR, 1)
lstm2_persist(const float* __restrict__ x,
              const float* __restrict__ w_ih0, const float* __restrict__ w_hh0,
              const float* __restrict__ b_ih0, const float* __restrict__ b_hh0,
              const float* __restrict__ w_ih1, const float* __restrict__ w_hh1,
              const float* __restrict__ b_ih1, const float* __restrict__ b_hh1,
              float* __restrict__ out) {
    extern __shared__ float smem[];

    // Phase A: xg = x @ w_ih0^T + b_ih0 + b_hh0   (x immutable -> plain LDG)
    gate_gemm_dev<LATENT, false>(w_ih0, x, b_ih0, b_hh0, g_xg, smem);
    grid_barrier();

    // Layer 0 recurrence
    lstm_layer_dev(w_hh0, g_xg, g_h1, nullptr);

    // Phase C: xg = h1 @ w_ih1^T + b_ih1 + b_hh1  (h1 mutable -> SMEM-stage via ld.cg)
    gate_gemm_dev<HID, true>(w_ih1, g_h1, b_ih1, b_hh1, g_xg, smem);
    grid_barrier();

    // Layer 1 recurrence -> out: [0:HID) last_output, [HID:) h2 rows
    lstm_layer_dev(w_hh1, g_xg, out + HID, out);
}

// ---------------- host launch (graph-capturable, single node) ---------------
extern "C" void kernel_launch(void* const* d_in, const int* in_sizes, int n_in,
                              void* d_out, int out_size) {
    const float* x     = (const float*)d_in[0];
    const float* w_ih0 = (const float*)d_in[1];
    const float* w_hh0 = (const float*)d_in[2];
    const float* b_ih0 = (const float*)d_in[3];
    const float* b_hh0 = (const float*)d_in[4];
    const float* w_ih1 = (const float*)d_in[5];
    const float* w_hh1 = (const float*)d_in[6];
    const float* b_ih1 = (const float*)d_in[7];
    const float* b_hh1 = (const float*)d_in[8];
    float* out = (float*)d_out;

    cudaFuncSetAttribute(lstm2_persist,
                         cudaFuncAttributeMaxDynamicSharedMemorySize, SMEM_BYTES);
    lstm2_persist<<<NCTA, NTHR, SMEM_BYTES>>>(x, w_ih0, w_hh0, b_ih0, b_hh0,
                                              w_ih1, w_hh1, b_ih1, b_hh1, out);
}